// round 4
// baseline (speedup 1.0000x reference)
#include <cuda_runtime.h>
#include <math.h>

#define B_  16
#define C_  512
#define HW_ 1024
#define C3_ 1536
#define NH_ 8
#define HC_ 64

static __device__ float g_norm[(size_t)2 * B_ * C_ * HW_];
static __device__ float g_t   [(size_t)2 * B_ * C3_ * HW_];
static __device__ float g_qkv [(size_t)2 * B_ * C3_ * HW_];
static __device__ float g_attn[(size_t)B_ * 2 * C_ * HW_];
static __device__ float g_stats[2 * B_ * 2];

// ---------------------------------------------------------------------------
// Kernel 1: per-sample LayerNorm statistics
// ---------------------------------------------------------------------------
__global__ void ln_stats(const float* __restrict__ img, const float* __restrict__ wm) {
    int blk = blockIdx.x;
    int s = blk >> 4, b = blk & 15;
    const float* x = (s ? wm : img) + (size_t)b * C_ * HW_;
    float sum = 0.f, sq = 0.f;
    for (int i = threadIdx.x; i < C_ * HW_; i += blockDim.x) {
        float v = x[i];
        sum += v; sq += v * v;
    }
    __shared__ float s1[512], s2[512];
    s1[threadIdx.x] = sum; s2[threadIdx.x] = sq;
    __syncthreads();
    for (int st = 256; st > 0; st >>= 1) {
        if (threadIdx.x < st) {
            s1[threadIdx.x] += s1[threadIdx.x + st];
            s2[threadIdx.x] += s2[threadIdx.x + st];
        }
        __syncthreads();
    }
    if (threadIdx.x == 0) {
        float inv_n = 1.f / (float)(C_ * HW_);
        float mu  = s1[0] * inv_n;
        float var = s2[0] * inv_n - mu * mu;
        g_stats[blk * 2 + 0] = mu;
        g_stats[blk * 2 + 1] = rsqrtf(var + 1e-5f);
    }
}

// ---------------------------------------------------------------------------
// Kernel 2: apply LN affine
// ---------------------------------------------------------------------------
__global__ void ln_apply(const float* __restrict__ img, const float* __restrict__ wm,
                         const float* __restrict__ iw, const float* __restrict__ ib,
                         const float* __restrict__ ww, const float* __restrict__ wb) {
    size_t idx = (size_t)blockIdx.x * blockDim.x + threadIdx.x;
    const size_t half = (size_t)B_ * C_ * HW_;
    if (idx >= 2 * half) return;
    int s = idx >= half;
    size_t r = idx - (size_t)s * half;
    int b = (int)(r / ((size_t)C_ * HW_));
    int chw = (int)(r % ((size_t)C_ * HW_));
    const float* x  = s ? wm : img;
    const float* w  = s ? ww : iw;
    const float* bb = s ? wb : ib;
    float mu   = g_stats[(s * 16 + b) * 2 + 0];
    float rstd = g_stats[(s * 16 + b) * 2 + 1];
    g_norm[idx] = (x[(size_t)b * C_ * HW_ + chw] - mu) * rstd * w[chw] + bb[chw];
}

// ---------------------------------------------------------------------------
// tf32 helpers
// ---------------------------------------------------------------------------
__device__ __forceinline__ unsigned f2tf32(float f) {
    unsigned r; asm("cvt.rna.tf32.f32 %0, %1;" : "=r"(r) : "f"(f)); return r;
}
__device__ __forceinline__ void mma_tf32(float* c, const unsigned* a, const unsigned* b) {
    asm volatile(
        "mma.sync.aligned.m16n8k8.row.col.f32.tf32.tf32.f32 "
        "{%0,%1,%2,%3}, {%4,%5,%6,%7}, {%8,%9}, {%0,%1,%2,%3};"
        : "+f"(c[0]), "+f"(c[1]), "+f"(c[2]), "+f"(c[3])
        : "r"(a[0]), "r"(a[1]), "r"(a[2]), "r"(a[3]), "r"(b[0]), "r"(b[1]));
}
__device__ __forceinline__ void mma_u(float* c, unsigned a0, unsigned a1, unsigned a2,
                                      unsigned a3, unsigned b0, unsigned b1) {
    asm volatile(
        "mma.sync.aligned.m16n8k8.row.col.f32.tf32.tf32.f32 "
        "{%0,%1,%2,%3}, {%4,%5,%6,%7}, {%8,%9}, {%0,%1,%2,%3};"
        : "+f"(c[0]), "+f"(c[1]), "+f"(c[2]), "+f"(c[3])
        : "r"(a0), "r"(a1), "r"(a2), "r"(a3), "r"(b0), "r"(b1));
}

struct alignas(8) u2 { unsigned hi, lo; };

__device__ __forceinline__ u2 split_tf32(float x) {
    u2 r;
    asm("cvt.rna.tf32.f32 %0, %1;" : "=r"(r.hi) : "f"(x));
    float d = x - __uint_as_float(r.hi);
    asm("cvt.rna.tf32.f32 %0, %1;" : "=r"(r.lo) : "f"(d));
    return r;
}

__device__ __forceinline__ void cp16(void* sdst, const void* gsrc) {
    unsigned s = (unsigned)__cvta_generic_to_shared(sdst);
    asm volatile("cp.async.cg.shared.global [%0], [%1], 16;" :: "r"(s), "l"(gsrc));
}

// ---------------------------------------------------------------------------
// Kernel 3/6: tf32 TC GEMM, cp.async double-buffered, cvt after LDS.
//   Block 128x128, kTile 16, 256 threads, warp tile 32x64.
// ---------------------------------------------------------------------------
template <bool TA>
__global__ __launch_bounds__(256)
void gemm_tc(const float* __restrict__ A, const float* __restrict__ Bm,
             float* __restrict__ Cm, const float* __restrict__ bias,
             int M, int N, int K, size_t strideB, size_t strideC) {
    __shared__ float As[2][2560];     // TA=false: [128][20]; TA=true: [16][132]
    __shared__ float Bs[2][16 * 132];
    const float* Bb = Bm + (size_t)blockIdx.z * strideB;
    float* Cb = Cm + (size_t)blockIdx.z * strideC;
    int m0 = blockIdx.y * 128, n0 = blockIdx.x * 128;
    int tid = threadIdx.x, lane = tid & 31, wid = tid >> 5;
    int warpM = wid & 3, warpN = wid >> 2;
    int gi = lane >> 2, li = lane & 3;

    float acc[2][8][4];
#pragma unroll
    for (int mi = 0; mi < 2; mi++)
#pragma unroll
        for (int ni = 0; ni < 8; ni++)
#pragma unroll
            for (int j = 0; j < 4; j++) acc[mi][ni][j] = 0.f;

    const int T = K / 16;

#define COPY_TILE(t, buf)                                                        \
    {                                                                            \
        int k0c = (t) * 16;                                                      \
        _Pragma("unroll")                                                        \
        for (int r = 0; r < 2; r++) {                                            \
            int idx = tid + r * 256;                                             \
            if (TA) {                                                            \
                int kl = idx >> 5, mq = idx & 31;                                \
                cp16(&As[buf][kl * 132 + mq * 4],                                \
                     &A[(size_t)(k0c + kl) * M + m0 + mq * 4]);                  \
            } else {                                                             \
                int ml = idx >> 2, kq = idx & 3;                                 \
                cp16(&As[buf][ml * 20 + kq * 4],                                 \
                     &A[(size_t)(m0 + ml) * K + k0c + kq * 4]);                  \
            }                                                                    \
            int kl = idx >> 5, nq = idx & 31;                                    \
            cp16(&Bs[buf][kl * 132 + nq * 4],                                    \
                 &Bb[(size_t)(k0c + kl) * N + n0 + nq * 4]);                     \
        }                                                                        \
        asm volatile("cp.async.commit_group;");                                  \
    }

    COPY_TILE(0, 0);

    for (int t = 0; t < T; t++) {
        int buf = t & 1;
        __syncthreads();                 // compute(t-1) done before refill of buf^1
        if (t + 1 < T) {
            COPY_TILE(t + 1, buf ^ 1);
            asm volatile("cp.async.wait_group 1;");
        } else {
            asm volatile("cp.async.wait_group 0;");
        }
        __syncthreads();
#pragma unroll
        for (int ks = 0; ks < 2; ks++) {
            int k8 = ks * 8;
            unsigned ua[2][4];
#pragma unroll
            for (int mi = 0; mi < 2; mi++) {
                int m = warpM * 32 + mi * 16 + gi;
                float f0, f1, f2, f3;
                if (TA) {
                    f0 = As[buf][(k8 + li) * 132 + m];
                    f1 = As[buf][(k8 + li) * 132 + m + 8];
                    f2 = As[buf][(k8 + li + 4) * 132 + m];
                    f3 = As[buf][(k8 + li + 4) * 132 + m + 8];
                } else {
                    f0 = As[buf][m * 20 + k8 + li];
                    f1 = As[buf][(m + 8) * 20 + k8 + li];
                    f2 = As[buf][m * 20 + k8 + li + 4];
                    f3 = As[buf][(m + 8) * 20 + k8 + li + 4];
                }
                ua[mi][0] = f2tf32(f0); ua[mi][1] = f2tf32(f1);
                ua[mi][2] = f2tf32(f2); ua[mi][3] = f2tf32(f3);
            }
            unsigned ub[8][2];
#pragma unroll
            for (int ni = 0; ni < 8; ni++) {
                int nn = warpN * 64 + ni * 8 + gi;
                ub[ni][0] = f2tf32(Bs[buf][(k8 + li) * 132 + nn]);
                ub[ni][1] = f2tf32(Bs[buf][(k8 + li + 4) * 132 + nn]);
            }
#pragma unroll
            for (int mi = 0; mi < 2; mi++)
#pragma unroll
                for (int ni = 0; ni < 8; ni++)
                    mma_tf32(acc[mi][ni], ua[mi], ub[ni]);
        }
    }

#pragma unroll
    for (int mi = 0; mi < 2; mi++) {
        int mrow = m0 + warpM * 32 + mi * 16 + gi;
        float bv0 = bias ? bias[mrow] : 0.f;
        float bv1 = bias ? bias[mrow + 8] : 0.f;
#pragma unroll
        for (int ni = 0; ni < 8; ni++) {
            int n = n0 + warpN * 64 + ni * 8 + 2 * li;
            float2 v0 = {acc[mi][ni][0] + bv0, acc[mi][ni][1] + bv0};
            float2 v1 = {acc[mi][ni][2] + bv1, acc[mi][ni][3] + bv1};
            *(float2*)&Cb[(size_t)mrow * N + n] = v0;
            *(float2*)&Cb[(size_t)(mrow + 8) * N + n] = v1;
        }
    }
}

// ---------------------------------------------------------------------------
// Kernel 4: grouped 3x3 conv, smem-tiled
// ---------------------------------------------------------------------------
__global__ __launch_bounds__(256)
void dwconv_kernel(const float* __restrict__ wimg, const float* __restrict__ bimg,
                   const float* __restrict__ wwm,  const float* __restrict__ bwm) {
    __shared__ float sin_[3][HW_];
    __shared__ float sw[81];
    __shared__ float sbias[3];
    int blk = blockIdx.x;
    int g = blk & 511, sb = blk >> 9;
    int s = sb >> 4;
    int tid = threadIdx.x;
    const float* in = g_t + ((size_t)sb * C3_ + g * 3) * HW_;
#pragma unroll
    for (int r = 0; r < 3; r++) {
        int idx = tid + r * 256;
        ((float4*)sin_)[idx] = ((const float4*)in)[idx];
    }
    const float* w = (s ? wwm : wimg) + (size_t)g * 81;
    if (tid < 81) sw[tid] = w[tid];
    if (tid < 3) sbias[tid] = (s ? bwm : bimg)[g * 3 + tid];
    __syncthreads();
    float* outp = g_qkv + ((size_t)sb * C3_ + g * 3) * HW_;
#pragma unroll
    for (int o = 0; o < 3; o++) {
#pragma unroll
        for (int r = 0; r < 4; r++) {
            int hw = tid + r * 256;
            int y = hw >> 5, x = hw & 31;
            float accv = sbias[o];
#pragma unroll
            for (int i = 0; i < 3; i++)
#pragma unroll
                for (int ky = 0; ky < 3; ky++) {
                    int yy = y + ky - 1;
                    if (yy < 0 || yy >= 32) continue;
#pragma unroll
                    for (int kx = 0; kx < 3; kx++) {
                        int xx = x + kx - 1;
                        if (xx < 0 || xx >= 32) continue;
                        accv += sw[o * 27 + i * 9 + ky * 3 + kx] * sin_[i][yy * 32 + xx];
                    }
                }
            outp[(size_t)o * HW_ + hw] = accv;
        }
    }
}

// ---------------------------------------------------------------------------
// Kernel 5: TC cross-attention, tf32x3. 512 threads, 2 blocks/SM (one wave).
//   S split to hi/lo ONCE (in softmax); phase 3 reads split S directly.
// smem: KV u2[128][36] (K phase1 / V phase3) ; S2 u2[128][72] (Q alias rows 0-31)
// ---------------------------------------------------------------------------
#define KVST 36
#define QST  72
#define S2ST 72
#define SMEM_S2_OFF  (128 * KVST * 8)                  // 36864
#define SMEM_ATTN    (SMEM_S2_OFF + 128 * S2ST * 8)    // 110592

__global__ __launch_bounds__(512)
void attn_tc_kernel() {
    extern __shared__ char smem_raw[];
    u2* KV = (u2*)smem_raw;
    u2* S2 = (u2*)(smem_raw + SMEM_S2_OFF);
    u2* Qs = S2;   // alias: Q staging lives in S2 rows 0-31 during phase 1

    int bid = blockIdx.x;
    int s = bid & 1, n = (bid >> 1) & 7, b = bid >> 4;
    int tid = threadIdx.x, lane = tid & 31, w = tid >> 5;
    int gi = lane >> 2, li = lane & 3;

    const size_t SB = (size_t)B_ * C3_ * HW_;
    const float* qbase  = g_qkv + (s ? SB : 0) + ((size_t)b * C3_ + n * HC_) * HW_;
    const float* k0base = g_qkv + ((size_t)b * C3_ + C_ + n * HC_) * HW_;
    const float* k1base = k0base + SB;
    const float* v0base = g_qkv + ((size_t)b * C3_ + 2 * C_ + n * HC_) * HW_;
    const float* v1base = v0base + SB;

    // ======== Phase 1: S = K . Q^T  (contraction over p=1024) ========
    int wM = w & 3, wN = w >> 2;   // 4 k-groups of 32, 4 q-groups of 16
    float accS[2][2][4];
#pragma unroll
    for (int mi = 0; mi < 2; mi++)
#pragma unroll
        for (int ni = 0; ni < 2; ni++)
#pragma unroll
            for (int j = 0; j < 4; j++) accS[mi][ni][j] = 0.f;

    for (int pc = 0; pc < 32; pc++) {
        int p0 = pc * 32;
        __syncthreads();
#pragma unroll
        for (int i = 0; i < 2; i++) {
            int idx = tid + i * 512;
            int kr = idx >> 3, quad = idx & 7;
            const float* krow = (kr < 64) ? k0base + (size_t)kr * HW_
                                          : k1base + (size_t)(kr - 64) * HW_;
            float4 v = *(const float4*)&krow[p0 + quad * 4];
            u2 s0 = split_tf32(v.x), s1 = split_tf32(v.y);
            u2 s2 = split_tf32(v.z), s3 = split_tf32(v.w);
            uint4* d = (uint4*)&KV[kr * KVST + quad * 4];
            d[0] = make_uint4(s0.hi, s0.lo, s1.hi, s1.lo);
            d[1] = make_uint4(s2.hi, s2.lo, s3.hi, s3.lo);
        }
        {
            int qr = tid >> 3, quad = tid & 7;
            float4 v = *(const float4*)&qbase[(size_t)qr * HW_ + p0 + quad * 4];
            Qs[(quad * 4 + 0) * QST + qr] = split_tf32(v.x);
            Qs[(quad * 4 + 1) * QST + qr] = split_tf32(v.y);
            Qs[(quad * 4 + 2) * QST + qr] = split_tf32(v.z);
            Qs[(quad * 4 + 3) * QST + qr] = split_tf32(v.w);
        }
        __syncthreads();
#pragma unroll
        for (int ks = 0; ks < 4; ks++) {
            int p8 = ks * 8;
            u2 a[2][4], bq[2][2];
#pragma unroll
            for (int mi = 0; mi < 2; mi++) {
                int m = wM * 32 + mi * 16 + gi;
                a[mi][0] = KV[m * KVST + p8 + li];
                a[mi][1] = KV[(m + 8) * KVST + p8 + li];
                a[mi][2] = KV[m * KVST + p8 + li + 4];
                a[mi][3] = KV[(m + 8) * KVST + p8 + li + 4];
            }
#pragma unroll
            for (int ni = 0; ni < 2; ni++) {
                int q = wN * 16 + ni * 8 + gi;
                bq[ni][0] = Qs[(p8 + li) * QST + q];
                bq[ni][1] = Qs[(p8 + li + 4) * QST + q];
            }
#pragma unroll
            for (int mi = 0; mi < 2; mi++)
#pragma unroll
                for (int ni = 0; ni < 2; ni++) {
                    float* c = accS[mi][ni];
                    mma_u(c, a[mi][0].hi, a[mi][1].hi, a[mi][2].hi, a[mi][3].hi,
                          bq[ni][0].hi, bq[ni][1].hi);
                    mma_u(c, a[mi][0].hi, a[mi][1].hi, a[mi][2].hi, a[mi][3].hi,
                          bq[ni][0].lo, bq[ni][1].lo);
                    mma_u(c, a[mi][0].lo, a[mi][1].lo, a[mi][2].lo, a[mi][3].lo,
                          bq[ni][0].hi, bq[ni][1].hi);
                }
        }
    }
    __syncthreads();   // all reads of Qs done before S2 overwrite
#pragma unroll
    for (int mi = 0; mi < 2; mi++)
#pragma unroll
        for (int ni = 0; ni < 2; ni++) {
            int m = wM * 32 + mi * 16 + gi;
            int q0 = wN * 16 + ni * 8 + 2 * li;
            S2[m * S2ST + q0]           = split_tf32(accS[mi][ni][0]);
            S2[m * S2ST + q0 + 1]       = split_tf32(accS[mi][ni][1]);
            S2[(m + 8) * S2ST + q0]     = split_tf32(accS[mi][ni][2]);
            S2[(m + 8) * S2ST + q0 + 1] = split_tf32(accS[mi][ni][3]);
        }
    __syncthreads();

    // ======== Phase 2: softmax over q per k-row; store split probs ========
    if (tid < 128) {
        u2* row = &S2[tid * S2ST];
        float mx = -1e30f;
#pragma unroll 8
        for (int j = 0; j < 64; j++) {
            u2 v = row[j];
            mx = fmaxf(mx, __uint_as_float(v.hi) + __uint_as_float(v.lo));
        }
        float sum = 0.f;
#pragma unroll 8
        for (int j = 0; j < 64; j++) {
            u2 v = row[j];
            float e = __expf(__uint_as_float(v.hi) + __uint_as_float(v.lo) - mx);
            sum += e;
            row[j] = split_tf32(e);
        }
        float inv = 1.f / sum;
#pragma unroll 8
        for (int j = 0; j < 64; j++) {
            u2 v = row[j];
            row[j] = split_tf32((__uint_as_float(v.hi) + __uint_as_float(v.lo)) * inv);
        }
    }

    // ======== Phase 3: out[q][p] = sum_k S[k][q] V[k][p] ========
    int wM3 = w & 3, wN3 = w >> 2;   // q-group of 16, p-group of 8
    float* outbase = g_attn + ((size_t)b * (2 * C_) + n * 128 + s * 64) * HW_;
    int m = wM3 * 16 + gi;
    int pl = wN3 * 8 + gi;
    for (int pc = 0; pc < 32; pc++) {
        int p0 = pc * 32;
        __syncthreads();
#pragma unroll
        for (int i = 0; i < 2; i++) {
            int idx = tid + i * 512;
            int kr = idx >> 3, quad = idx & 7;
            const float* vrow = (kr < 64) ? v0base + (size_t)kr * HW_
                                          : v1base + (size_t)(kr - 64) * HW_;
            float4 v = *(const float4*)&vrow[p0 + quad * 4];
            u2 s0 = split_tf32(v.x), s1 = split_tf32(v.y);
            u2 s2 = split_tf32(v.z), s3 = split_tf32(v.w);
            uint4* d = (uint4*)&KV[kr * KVST + quad * 4];
            d[0] = make_uint4(s0.hi, s0.lo, s1.hi, s1.lo);
            d[1] = make_uint4(s2.hi, s2.lo, s3.hi, s3.lo);
        }
        __syncthreads();
        float c[4] = {0.f, 0.f, 0.f, 0.f};
#pragma unroll
        for (int ks = 0; ks < 16; ks++) {
            int k8 = ks * 8;
            u2 a0 = S2[(k8 + li) * S2ST + m];
            u2 a1 = S2[(k8 + li) * S2ST + m + 8];
            u2 a2 = S2[(k8 + li + 4) * S2ST + m];
            u2 a3 = S2[(k8 + li + 4) * S2ST + m + 8];
            u2 b0 = KV[(k8 + li) * KVST + pl];
            u2 b1 = KV[(k8 + li + 4) * KVST + pl];
            mma_u(c, a0.hi, a1.hi, a2.hi, a3.hi, b0.hi, b1.hi);
            mma_u(c, a0.hi, a1.hi, a2.hi, a3.hi, b0.lo, b1.lo);
            mma_u(c, a0.lo, a1.lo, a2.lo, a3.lo, b0.hi, b1.hi);
        }
        int pcol = p0 + wN3 * 8 + 2 * li;
        float2 v0 = {c[0], c[1]};
        float2 v1 = {c[2], c[3]};
        *(float2*)&outbase[(size_t)m * HW_ + pcol] = v0;
        *(float2*)&outbase[(size_t)(m + 8) * HW_ + pcol] = v1;
    }
}

// ---------------------------------------------------------------------------
extern "C" void kernel_launch(void* const* d_in, const int* in_sizes, int n_in,
                              void* d_out, int out_size) {
    const float* image     = (const float*)d_in[0];
    const float* watermark = (const float*)d_in[1];
    const float* img_ln_w  = (const float*)d_in[2];
    const float* img_ln_b  = (const float*)d_in[3];
    const float* wm_ln_w   = (const float*)d_in[4];
    const float* wm_ln_b   = (const float*)d_in[5];
    const float* img_pw_w  = (const float*)d_in[6];
    const float* img_pw_b  = (const float*)d_in[7];
    const float* img_dw_w  = (const float*)d_in[8];
    const float* img_dw_b  = (const float*)d_in[9];
    const float* wm_pw_w   = (const float*)d_in[10];
    const float* wm_pw_b   = (const float*)d_in[11];
    const float* wm_dw_w   = (const float*)d_in[12];
    const float* wm_dw_b   = (const float*)d_in[13];
    const float* proj      = (const float*)d_in[14];
    float* out = (float*)d_out;

    float *p_norm, *p_t, *p_attn;
    cudaGetSymbolAddress((void**)&p_norm, g_norm);
    cudaGetSymbolAddress((void**)&p_t,    g_t);
    cudaGetSymbolAddress((void**)&p_attn, g_attn);

    cudaFuncSetAttribute(attn_tc_kernel,
                         cudaFuncAttributeMaxDynamicSharedMemorySize, SMEM_ATTN);

    // 1) LayerNorm
    ln_stats<<<32, 512>>>(image, watermark);
    size_t totalN = (size_t)2 * B_ * C_ * HW_;
    ln_apply<<<(unsigned)((totalN + 255) / 256), 256>>>(
        image, watermark, img_ln_w, img_ln_b, wm_ln_w, wm_ln_b);

    // 2) Pointwise 1x1 conv (tf32 TC GEMM + cp.async)
    dim3 gpw(HW_ / 128, C3_ / 128, B_);
    gemm_tc<false><<<gpw, 256>>>(img_pw_w, p_norm, p_t, img_pw_b,
                                 C3_, HW_, C_, (size_t)C_ * HW_, (size_t)C3_ * HW_);
    gemm_tc<false><<<gpw, 256>>>(wm_pw_w, p_norm + (size_t)B_ * C_ * HW_,
                                 p_t + (size_t)B_ * C3_ * HW_, wm_pw_b,
                                 C3_, HW_, C_, (size_t)C_ * HW_, (size_t)C3_ * HW_);

    // 3) Grouped 3x3 conv
    dwconv_kernel<<<32 * 512, 256>>>(img_dw_w, img_dw_b, wm_dw_w, wm_dw_b);

    // 4) Cross-attention (512 threads, 2 blocks/SM, one wave)
    attn_tc_kernel<<<B_ * NH_ * 2, 512, SMEM_ATTN>>>();

    // 5) Final projection GEMM
    dim3 gf(HW_ / 128, C_ / 128, B_);
    gemm_tc<true><<<gf, 256>>>(proj, p_attn, out, nullptr,
                               C_, HW_, 2 * C_, (size_t)2 * C_ * HW_, (size_t)C_ * HW_);
}

// round 5
// speedup vs baseline: 1.0747x; 1.0747x over previous
#include <cuda_runtime.h>
#include <math.h>

#define B_  16
#define C_  512
#define HW_ 1024
#define C3_ 1536
#define NH_ 8
#define HC_ 64

static __device__ float g_norm[(size_t)2 * B_ * C_ * HW_];
static __device__ float g_t   [(size_t)2 * B_ * C3_ * HW_];
static __device__ float g_qkv [(size_t)2 * B_ * C3_ * HW_];
static __device__ float g_attn[(size_t)B_ * 2 * C_ * HW_];
static __device__ float g_stats[2 * B_ * 2];

// ---------------------------------------------------------------------------
// Kernel 1: per-sample LayerNorm statistics
// ---------------------------------------------------------------------------
__global__ void ln_stats(const float* __restrict__ img, const float* __restrict__ wm) {
    int blk = blockIdx.x;
    int s = blk >> 4, b = blk & 15;
    const float* x = (s ? wm : img) + (size_t)b * C_ * HW_;
    float sum = 0.f, sq = 0.f;
    for (int i = threadIdx.x; i < C_ * HW_; i += blockDim.x) {
        float v = x[i];
        sum += v; sq += v * v;
    }
    __shared__ float s1[512], s2[512];
    s1[threadIdx.x] = sum; s2[threadIdx.x] = sq;
    __syncthreads();
    for (int st = 256; st > 0; st >>= 1) {
        if (threadIdx.x < st) {
            s1[threadIdx.x] += s1[threadIdx.x + st];
            s2[threadIdx.x] += s2[threadIdx.x + st];
        }
        __syncthreads();
    }
    if (threadIdx.x == 0) {
        float inv_n = 1.f / (float)(C_ * HW_);
        float mu  = s1[0] * inv_n;
        float var = s2[0] * inv_n - mu * mu;
        g_stats[blk * 2 + 0] = mu;
        g_stats[blk * 2 + 1] = rsqrtf(var + 1e-5f);
    }
}

// ---------------------------------------------------------------------------
// Kernel 2: apply LN affine
// ---------------------------------------------------------------------------
__global__ void ln_apply(const float* __restrict__ img, const float* __restrict__ wm,
                         const float* __restrict__ iw, const float* __restrict__ ib,
                         const float* __restrict__ ww, const float* __restrict__ wb) {
    size_t idx = (size_t)blockIdx.x * blockDim.x + threadIdx.x;
    const size_t half = (size_t)B_ * C_ * HW_;
    if (idx >= 2 * half) return;
    int s = idx >= half;
    size_t r = idx - (size_t)s * half;
    int b = (int)(r / ((size_t)C_ * HW_));
    int chw = (int)(r % ((size_t)C_ * HW_));
    const float* x  = s ? wm : img;
    const float* w  = s ? ww : iw;
    const float* bb = s ? wb : ib;
    float mu   = g_stats[(s * 16 + b) * 2 + 0];
    float rstd = g_stats[(s * 16 + b) * 2 + 1];
    g_norm[idx] = (x[(size_t)b * C_ * HW_ + chw] - mu) * rstd * w[chw] + bb[chw];
}

// ---------------------------------------------------------------------------
// tf32 helpers
// ---------------------------------------------------------------------------
__device__ __forceinline__ unsigned f2tf32(float f) {
    unsigned r; asm("cvt.rna.tf32.f32 %0, %1;" : "=r"(r) : "f"(f)); return r;
}
__device__ __forceinline__ void mma_tf32(float* c, const unsigned* a, const unsigned* b) {
    asm volatile(
        "mma.sync.aligned.m16n8k8.row.col.f32.tf32.tf32.f32 "
        "{%0,%1,%2,%3}, {%4,%5,%6,%7}, {%8,%9}, {%0,%1,%2,%3};"
        : "+f"(c[0]), "+f"(c[1]), "+f"(c[2]), "+f"(c[3])
        : "r"(a[0]), "r"(a[1]), "r"(a[2]), "r"(a[3]), "r"(b[0]), "r"(b[1]));
}
__device__ __forceinline__ void mma_u(float* c, unsigned a0, unsigned a1, unsigned a2,
                                      unsigned a3, unsigned b0, unsigned b1) {
    asm volatile(
        "mma.sync.aligned.m16n8k8.row.col.f32.tf32.tf32.f32 "
        "{%0,%1,%2,%3}, {%4,%5,%6,%7}, {%8,%9}, {%0,%1,%2,%3};"
        : "+f"(c[0]), "+f"(c[1]), "+f"(c[2]), "+f"(c[3])
        : "r"(a0), "r"(a1), "r"(a2), "r"(a3), "r"(b0), "r"(b1));
}

struct alignas(8) u2 { unsigned hi, lo; };

__device__ __forceinline__ u2 split_tf32(float x) {
    u2 r;
    asm("cvt.rna.tf32.f32 %0, %1;" : "=r"(r.hi) : "f"(x));
    float d = x - __uint_as_float(r.hi);
    asm("cvt.rna.tf32.f32 %0, %1;" : "=r"(r.lo) : "f"(d));
    return r;
}

__device__ __forceinline__ void cp16(void* sdst, const void* gsrc) {
    unsigned s = (unsigned)__cvta_generic_to_shared(sdst);
    asm volatile("cp.async.cg.shared.global [%0], [%1], 16;" :: "r"(s), "l"(gsrc));
}

// ---------------------------------------------------------------------------
// Kernel 3/6: tf32 TC GEMM, cp.async double-buffered, cvt after LDS.
//   Block 128x128, kTile 16, 256 threads, warp tile 32x64. (Round-4 version)
// ---------------------------------------------------------------------------
template <bool TA>
__global__ __launch_bounds__(256)
void gemm_tc(const float* __restrict__ A, const float* __restrict__ Bm,
             float* __restrict__ Cm, const float* __restrict__ bias,
             int M, int N, int K, size_t strideB, size_t strideC) {
    __shared__ float As[2][2560];     // TA=false: [128][20]; TA=true: [16][132]
    __shared__ float Bs[2][16 * 132];
    const float* Bb = Bm + (size_t)blockIdx.z * strideB;
    float* Cb = Cm + (size_t)blockIdx.z * strideC;
    int m0 = blockIdx.y * 128, n0 = blockIdx.x * 128;
    int tid = threadIdx.x, lane = tid & 31, wid = tid >> 5;
    int warpM = wid & 3, warpN = wid >> 2;
    int gi = lane >> 2, li = lane & 3;

    float acc[2][8][4];
#pragma unroll
    for (int mi = 0; mi < 2; mi++)
#pragma unroll
        for (int ni = 0; ni < 8; ni++)
#pragma unroll
            for (int j = 0; j < 4; j++) acc[mi][ni][j] = 0.f;

    const int T = K / 16;

#define COPY_TILE(t, buf)                                                        \
    {                                                                            \
        int k0c = (t) * 16;                                                      \
        _Pragma("unroll")                                                        \
        for (int r = 0; r < 2; r++) {                                            \
            int idx = tid + r * 256;                                             \
            if (TA) {                                                            \
                int kl = idx >> 5, mq = idx & 31;                                \
                cp16(&As[buf][kl * 132 + mq * 4],                                \
                     &A[(size_t)(k0c + kl) * M + m0 + mq * 4]);                  \
            } else {                                                             \
                int ml = idx >> 2, kq = idx & 3;                                 \
                cp16(&As[buf][ml * 20 + kq * 4],                                 \
                     &A[(size_t)(m0 + ml) * K + k0c + kq * 4]);                  \
            }                                                                    \
            int kl = idx >> 5, nq = idx & 31;                                    \
            cp16(&Bs[buf][kl * 132 + nq * 4],                                    \
                 &Bb[(size_t)(k0c + kl) * N + n0 + nq * 4]);                     \
        }                                                                        \
        asm volatile("cp.async.commit_group;");                                  \
    }

    COPY_TILE(0, 0);

    for (int t = 0; t < T; t++) {
        int buf = t & 1;
        __syncthreads();
        if (t + 1 < T) {
            COPY_TILE(t + 1, buf ^ 1);
            asm volatile("cp.async.wait_group 1;");
        } else {
            asm volatile("cp.async.wait_group 0;");
        }
        __syncthreads();
#pragma unroll
        for (int ks = 0; ks < 2; ks++) {
            int k8 = ks * 8;
            unsigned ua[2][4];
#pragma unroll
            for (int mi = 0; mi < 2; mi++) {
                int m = warpM * 32 + mi * 16 + gi;
                float f0, f1, f2, f3;
                if (TA) {
                    f0 = As[buf][(k8 + li) * 132 + m];
                    f1 = As[buf][(k8 + li) * 132 + m + 8];
                    f2 = As[buf][(k8 + li + 4) * 132 + m];
                    f3 = As[buf][(k8 + li + 4) * 132 + m + 8];
                } else {
                    f0 = As[buf][m * 20 + k8 + li];
                    f1 = As[buf][(m + 8) * 20 + k8 + li];
                    f2 = As[buf][m * 20 + k8 + li + 4];
                    f3 = As[buf][(m + 8) * 20 + k8 + li + 4];
                }
                ua[mi][0] = f2tf32(f0); ua[mi][1] = f2tf32(f1);
                ua[mi][2] = f2tf32(f2); ua[mi][3] = f2tf32(f3);
            }
            unsigned ub[8][2];
#pragma unroll
            for (int ni = 0; ni < 8; ni++) {
                int nn = warpN * 64 + ni * 8 + gi;
                ub[ni][0] = f2tf32(Bs[buf][(k8 + li) * 132 + nn]);
                ub[ni][1] = f2tf32(Bs[buf][(k8 + li + 4) * 132 + nn]);
            }
#pragma unroll
            for (int mi = 0; mi < 2; mi++)
#pragma unroll
                for (int ni = 0; ni < 8; ni++)
                    mma_tf32(acc[mi][ni], ua[mi], ub[ni]);
        }
    }

#pragma unroll
    for (int mi = 0; mi < 2; mi++) {
        int mrow = m0 + warpM * 32 + mi * 16 + gi;
        float bv0 = bias ? bias[mrow] : 0.f;
        float bv1 = bias ? bias[mrow + 8] : 0.f;
#pragma unroll
        for (int ni = 0; ni < 8; ni++) {
            int n = n0 + warpN * 64 + ni * 8 + 2 * li;
            float2 v0 = {acc[mi][ni][0] + bv0, acc[mi][ni][1] + bv0};
            float2 v1 = {acc[mi][ni][2] + bv1, acc[mi][ni][3] + bv1};
            *(float2*)&Cb[(size_t)mrow * N + n] = v0;
            *(float2*)&Cb[(size_t)(mrow + 8) * N + n] = v1;
        }
    }
}

// ---------------------------------------------------------------------------
// Kernel 4: grouped 3x3 conv, smem-tiled
// ---------------------------------------------------------------------------
__global__ __launch_bounds__(256)
void dwconv_kernel(const float* __restrict__ wimg, const float* __restrict__ bimg,
                   const float* __restrict__ wwm,  const float* __restrict__ bwm) {
    __shared__ float sin_[3][HW_];
    __shared__ float sw[81];
    __shared__ float sbias[3];
    int blk = blockIdx.x;
    int g = blk & 511, sb = blk >> 9;
    int s = sb >> 4;
    int tid = threadIdx.x;
    const float* in = g_t + ((size_t)sb * C3_ + g * 3) * HW_;
#pragma unroll
    for (int r = 0; r < 3; r++) {
        int idx = tid + r * 256;
        ((float4*)sin_)[idx] = ((const float4*)in)[idx];
    }
    const float* w = (s ? wwm : wimg) + (size_t)g * 81;
    if (tid < 81) sw[tid] = w[tid];
    if (tid < 3) sbias[tid] = (s ? bwm : bimg)[g * 3 + tid];
    __syncthreads();
    float* outp = g_qkv + ((size_t)sb * C3_ + g * 3) * HW_;
#pragma unroll
    for (int o = 0; o < 3; o++) {
#pragma unroll
        for (int r = 0; r < 4; r++) {
            int hw = tid + r * 256;
            int y = hw >> 5, x = hw & 31;
            float accv = sbias[o];
#pragma unroll
            for (int i = 0; i < 3; i++)
#pragma unroll
                for (int ky = 0; ky < 3; ky++) {
                    int yy = y + ky - 1;
                    if (yy < 0 || yy >= 32) continue;
#pragma unroll
                    for (int kx = 0; kx < 3; kx++) {
                        int xx = x + kx - 1;
                        if (xx < 0 || xx >= 32) continue;
                        accv += sw[o * 27 + i * 9 + ky * 3 + kx] * sin_[i][yy * 32 + xx];
                    }
                }
            outp[(size_t)o * HW_ + hw] = accv;
        }
    }
}

// ---------------------------------------------------------------------------
// Kernel 5: TC cross-attention, tf32x3 (Round-3 tiling, 256 threads) with
//   split-once S: probs split to hi/lo in softmax, stored as u2.
// smem: KV u2[128][35]  (K phase1 / V phase3)
//       S2 u2[128][72]  (Q staging aliases rows 0-31 during phase 1)
// ---------------------------------------------------------------------------
#define KVST 35
#define QST  72
#define S2ST 72
#define SMEM_S2_OFF  (128 * KVST * 8)                  // 35840
#define SMEM_ATTN    (SMEM_S2_OFF + 128 * S2ST * 8)    // 109568

__global__ __launch_bounds__(256)
void attn_tc_kernel() {
    extern __shared__ char smem_raw[];
    u2* KV = (u2*)smem_raw;
    u2* S2 = (u2*)(smem_raw + SMEM_S2_OFF);
    u2* Qs = S2;   // alias: Q staging in S2 rows 0-31 during phase 1

    int bid = blockIdx.x;
    int s = bid & 1, n = (bid >> 1) & 7, b = bid >> 4;
    int tid = threadIdx.x, lane = tid & 31, w = tid >> 5;
    int gi = lane >> 2, li = lane & 3;

    const size_t SB = (size_t)B_ * C3_ * HW_;
    const float* qbase  = g_qkv + (s ? SB : 0) + ((size_t)b * C3_ + n * HC_) * HW_;
    const float* k0base = g_qkv + ((size_t)b * C3_ + C_ + n * HC_) * HW_;
    const float* k1base = k0base + SB;
    const float* v0base = g_qkv + ((size_t)b * C3_ + 2 * C_ + n * HC_) * HW_;
    const float* v1base = v0base + SB;

    // ======== Phase 1: S = K . Q^T (warp tile 32k x 32q) ========
    int wM = w & 3, wN = w >> 2;
    float accS[2][4][4];
#pragma unroll
    for (int mi = 0; mi < 2; mi++)
#pragma unroll
        for (int ni = 0; ni < 4; ni++)
#pragma unroll
            for (int j = 0; j < 4; j++) accS[mi][ni][j] = 0.f;

    for (int pc = 0; pc < 32; pc++) {
        int p0 = pc * 32;
        __syncthreads();
#pragma unroll
        for (int i = 0; i < 4; i++) {
            int idx = tid + i * 256;
            int kr = idx >> 3, quad = idx & 7;
            const float* krow = (kr < 64) ? k0base + (size_t)kr * HW_
                                          : k1base + (size_t)(kr - 64) * HW_;
            float4 v = *(const float4*)&krow[p0 + quad * 4];
            u2* dst = &KV[kr * KVST + quad * 4];
            dst[0] = split_tf32(v.x); dst[1] = split_tf32(v.y);
            dst[2] = split_tf32(v.z); dst[3] = split_tf32(v.w);
        }
#pragma unroll
        for (int i = 0; i < 2; i++) {
            int idx = tid + i * 256;
            int qr = idx >> 3, quad = idx & 7;
            float4 v = *(const float4*)&qbase[(size_t)qr * HW_ + p0 + quad * 4];
            Qs[(quad * 4 + 0) * QST + qr] = split_tf32(v.x);
            Qs[(quad * 4 + 1) * QST + qr] = split_tf32(v.y);
            Qs[(quad * 4 + 2) * QST + qr] = split_tf32(v.z);
            Qs[(quad * 4 + 3) * QST + qr] = split_tf32(v.w);
        }
        __syncthreads();
#pragma unroll
        for (int ks = 0; ks < 4; ks++) {
            int k8 = ks * 8;
            u2 a[2][4], bq[4][2];
#pragma unroll
            for (int mi = 0; mi < 2; mi++) {
                int m = wM * 32 + mi * 16 + gi;
                a[mi][0] = KV[m * KVST + k8 + li];
                a[mi][1] = KV[(m + 8) * KVST + k8 + li];
                a[mi][2] = KV[m * KVST + k8 + li + 4];
                a[mi][3] = KV[(m + 8) * KVST + k8 + li + 4];
            }
#pragma unroll
            for (int ni = 0; ni < 4; ni++) {
                int q = wN * 32 + ni * 8 + gi;
                bq[ni][0] = Qs[(k8 + li) * QST + q];
                bq[ni][1] = Qs[(k8 + li + 4) * QST + q];
            }
#pragma unroll
            for (int mi = 0; mi < 2; mi++)
#pragma unroll
                for (int ni = 0; ni < 4; ni++) {
                    float* c = accS[mi][ni];
                    mma_u(c, a[mi][0].hi, a[mi][1].hi, a[mi][2].hi, a[mi][3].hi,
                          bq[ni][0].hi, bq[ni][1].hi);
                    mma_u(c, a[mi][0].hi, a[mi][1].hi, a[mi][2].hi, a[mi][3].hi,
                          bq[ni][0].lo, bq[ni][1].lo);
                    mma_u(c, a[mi][0].lo, a[mi][1].lo, a[mi][2].lo, a[mi][3].lo,
                          bq[ni][0].hi, bq[ni][1].hi);
                }
        }
    }
    __syncthreads();   // all Qs reads complete before S2 overwrite
    // store S (split; phase 2 re-splits after softmax anyway)
#pragma unroll
    for (int mi = 0; mi < 2; mi++)
#pragma unroll
        for (int ni = 0; ni < 4; ni++) {
            int m = wM * 32 + mi * 16 + gi;
            int q0 = wN * 32 + ni * 8 + 2 * li;
            S2[m * S2ST + q0]           = split_tf32(accS[mi][ni][0]);
            S2[m * S2ST + q0 + 1]       = split_tf32(accS[mi][ni][1]);
            S2[(m + 8) * S2ST + q0]     = split_tf32(accS[mi][ni][2]);
            S2[(m + 8) * S2ST + q0 + 1] = split_tf32(accS[mi][ni][3]);
        }
    __syncthreads();

    // ======== Phase 2: softmax over q per k-row; store split probs ========
    if (tid < 128) {
        u2* row = &S2[tid * S2ST];
        float mx = -1e30f;
#pragma unroll 8
        for (int j = 0; j < 64; j++) {
            u2 v = row[j];
            mx = fmaxf(mx, __uint_as_float(v.hi) + __uint_as_float(v.lo));
        }
        float sum = 0.f;
        float ev[64];
#pragma unroll 8
        for (int j = 0; j < 64; j++) {
            u2 v = row[j];
            float e = __expf(__uint_as_float(v.hi) + __uint_as_float(v.lo) - mx);
            ev[j] = e; sum += e;
        }
        float inv = 1.f / sum;
#pragma unroll 8
        for (int j = 0; j < 64; j++) row[j] = split_tf32(ev[j] * inv);
    }

    // ======== Phase 3: out = S^T . V (warp tile 16q x 16p) ========
    int wM3 = w & 3, wN3 = w >> 2;
    float* outbase = g_attn + ((size_t)b * (2 * C_) + n * 128 + s * 64) * HW_;
    for (int pc = 0; pc < 32; pc++) {
        int p0 = pc * 32;
        __syncthreads();
#pragma unroll
        for (int i = 0; i < 4; i++) {
            int idx = tid + i * 256;
            int kr = idx >> 3, quad = idx & 7;
            const float* vrow = (kr < 64) ? v0base + (size_t)kr * HW_
                                          : v1base + (size_t)(kr - 64) * HW_;
            float4 v = *(const float4*)&vrow[p0 + quad * 4];
            u2* dst = &KV[kr * KVST + quad * 4];
            dst[0] = split_tf32(v.x); dst[1] = split_tf32(v.y);
            dst[2] = split_tf32(v.z); dst[3] = split_tf32(v.w);
        }
        __syncthreads();
        float acc3[2][4];
#pragma unroll
        for (int ni = 0; ni < 2; ni++)
#pragma unroll
            for (int j = 0; j < 4; j++) acc3[ni][j] = 0.f;
#pragma unroll
        for (int ks = 0; ks < 16; ks++) {
            int k8 = ks * 8;
            int m = wM3 * 16 + gi;
            u2 a0 = S2[(k8 + li) * S2ST + m];
            u2 a1 = S2[(k8 + li) * S2ST + m + 8];
            u2 a2 = S2[(k8 + li + 4) * S2ST + m];
            u2 a3 = S2[(k8 + li + 4) * S2ST + m + 8];
            u2 bv[2][2];
#pragma unroll
            for (int ni = 0; ni < 2; ni++) {
                int p = wN3 * 16 + ni * 8 + gi;
                bv[ni][0] = KV[(k8 + li) * KVST + p];
                bv[ni][1] = KV[(k8 + li + 4) * KVST + p];
            }
#pragma unroll
            for (int ni = 0; ni < 2; ni++) {
                float* c = acc3[ni];
                mma_u(c, a0.hi, a1.hi, a2.hi, a3.hi, bv[ni][0].hi, bv[ni][1].hi);
                mma_u(c, a0.hi, a1.hi, a2.hi, a3.hi, bv[ni][0].lo, bv[ni][1].lo);
                mma_u(c, a0.lo, a1.lo, a2.lo, a3.lo, bv[ni][0].hi, bv[ni][1].hi);
            }
        }
        int qrow = wM3 * 16 + gi;
#pragma unroll
        for (int ni = 0; ni < 2; ni++) {
            int p = p0 + wN3 * 16 + ni * 8 + 2 * li;
            float2 v0 = {acc3[ni][0], acc3[ni][1]};
            float2 v1 = {acc3[ni][2], acc3[ni][3]};
            *(float2*)&outbase[(size_t)qrow * HW_ + p] = v0;
            *(float2*)&outbase[(size_t)(qrow + 8) * HW_ + p] = v1;
        }
    }
}

// ---------------------------------------------------------------------------
extern "C" void kernel_launch(void* const* d_in, const int* in_sizes, int n_in,
                              void* d_out, int out_size) {
    const float* image     = (const float*)d_in[0];
    const float* watermark = (const float*)d_in[1];
    const float* img_ln_w  = (const float*)d_in[2];
    const float* img_ln_b  = (const float*)d_in[3];
    const float* wm_ln_w   = (const float*)d_in[4];
    const float* wm_ln_b   = (const float*)d_in[5];
    const float* img_pw_w  = (const float*)d_in[6];
    const float* img_pw_b  = (const float*)d_in[7];
    const float* img_dw_w  = (const float*)d_in[8];
    const float* img_dw_b  = (const float*)d_in[9];
    const float* wm_pw_w   = (const float*)d_in[10];
    const float* wm_pw_b   = (const float*)d_in[11];
    const float* wm_dw_w   = (const float*)d_in[12];
    const float* wm_dw_b   = (const float*)d_in[13];
    const float* proj      = (const float*)d_in[14];
    float* out = (float*)d_out;

    float *p_norm, *p_t, *p_attn;
    cudaGetSymbolAddress((void**)&p_norm, g_norm);
    cudaGetSymbolAddress((void**)&p_t,    g_t);
    cudaGetSymbolAddress((void**)&p_attn, g_attn);

    cudaFuncSetAttribute(attn_tc_kernel,
                         cudaFuncAttributeMaxDynamicSharedMemorySize, SMEM_ATTN);

    // 1) LayerNorm
    ln_stats<<<32, 512>>>(image, watermark);
    size_t totalN = (size_t)2 * B_ * C_ * HW_;
    ln_apply<<<(unsigned)((totalN + 255) / 256), 256>>>(
        image, watermark, img_ln_w, img_ln_b, wm_ln_w, wm_ln_b);

    // 2) Pointwise 1x1 conv (tf32 TC GEMM + cp.async)
    dim3 gpw(HW_ / 128, C3_ / 128, B_);
    gemm_tc<false><<<gpw, 256>>>(img_pw_w, p_norm, p_t, img_pw_b,
                                 C3_, HW_, C_, (size_t)C_ * HW_, (size_t)C3_ * HW_);
    gemm_tc<false><<<gpw, 256>>>(wm_pw_w, p_norm + (size_t)B_ * C_ * HW_,
                                 p_t + (size_t)B_ * C3_ * HW_, wm_pw_b,
                                 C3_, HW_, C_, (size_t)C_ * HW_, (size_t)C3_ * HW_);

    // 3) Grouped 3x3 conv
    dwconv_kernel<<<32 * 512, 256>>>(img_dw_w, img_dw_b, wm_dw_w, wm_dw_b);

    // 4) Cross-attention (256 threads, R3 tiling + split-once S)
    attn_tc_kernel<<<B_ * NH_ * 2, 256, SMEM_ATTN>>>();

    // 5) Final projection GEMM
    dim3 gf(HW_ / 128, C_ / 128, B_);
    gemm_tc<true><<<gf, 256>>>(proj, p_attn, out, nullptr,
                               C_, HW_, 2 * C_, (size_t)2 * C_ * HW_, (size_t)C_ * HW_);
}